// round 9
// baseline (speedup 1.0000x reference)
#include <cuda_runtime.h>
#include <cuda_bf16.h>
#include <cstdint>

// ---------------------------------------------------------------------------
// SEE block on GB300 — split architecture, smem-free GEMM.
// GEMM1: mma fragments loaded DIRECTLY from row-major global fp32 (LDG.64 +
//        in-register bf16 cvt). No smem, no syncs. y stored bf16.
// k_lif: depthwise conv+BN+LIF1 (tree conv, MLP=4) -> masks in smem ->
//        sparse linear+BN+LIF2+residual, chunk-level zero fast path.
// B=64, T=1000, F=140, D=256, K=7, tau=2, v_th=1, hard reset.
// ---------------------------------------------------------------------------

#define B_    64
#define T_    1000
#define F_    140
#define D_    256
#define K_    7
#define NCH   10
#define CLEN  100
#define WARM1 16
#define WARM2 16
#define SMT   (CLEN + WARM2)

__device__ __nv_bfloat16 g_ybf[(size_t)B_ * T_ * D_];  // GEMM out (B,T,D) bf16
__device__ float         g_linT[D_ * D_];              // lin_w^T [d][e]

__device__ __forceinline__ unsigned pack_bf16(float lo, float hi) {
    __nv_bfloat162 h = __floats2bfloat162_rn(lo, hi);
    return *reinterpret_cast<unsigned*>(&h);
}

// ---------------------------------------------------------------------------
// GEMM1: y[m,n] = x[m,:].pw_w[n,:],  M=64000 N=256 K=140 (9 k-steps of 16).
// Block = 128m x 128n, 8 warps (wm{0,1} x wn{0..3}), 2 m-tiles of 64.
// All fragments via LDG.64 from global + CVT; zero shared memory.
// ---------------------------------------------------------------------------
__global__ __launch_bounds__(256) void k_gemm1(const float* __restrict__ x,
                                               const float* __restrict__ w,
                                               const float* __restrict__ linw) {
    const int tid   = threadIdx.x;
    const int mbase = blockIdx.x * 128;
    const int n0    = blockIdx.y * 128;

    // folded transpose of lin_w
    if (blockIdx.y == 0 && blockIdx.x < D_) {
        int d = blockIdx.x;
        g_linT[d * D_ + tid] = linw[tid * D_ + d];
    }

    const int warp = tid >> 5, lane = tid & 31;
    const int wm = warp >> 2, wn = warp & 3;
    const int g  = lane >> 2, tig = lane & 3;

    float c[2][2][4][4];   // [mt][mi][ni][r]
    #pragma unroll
    for (int a = 0; a < 2; a++)
        #pragma unroll
        for (int b = 0; b < 2; b++)
            #pragma unroll
            for (int d = 0; d < 4; d++)
                #pragma unroll
                for (int r = 0; r < 4; r++) c[a][b][d][r] = 0.f;

    #pragma unroll
    for (int s = 0; s < 9; s++) {
        const int k0 = s * 16;
        const int kc = k0 + 2 * tig;          // frag col (even)
        const bool plo = (kc     < F_);       // compile-time after unroll
        const bool phi = (kc + 8 < F_);

        // ---- B fragments: 4 n-tiles x 2 regs ----
        unsigned bf[4][2];
        #pragma unroll
        for (int ni = 0; ni < 4; ni++) {
            const float* wp = w + (size_t)(n0 + wn * 32 + ni * 8 + g) * F_ + kc;
            float2 f0 = plo ? *(const float2*)wp       : make_float2(0.f, 0.f);
            float2 f1 = phi ? *(const float2*)(wp + 8) : make_float2(0.f, 0.f);
            bf[ni][0] = pack_bf16(f0.x, f0.y);
            bf[ni][1] = pack_bf16(f1.x, f1.y);
        }

        // ---- A fragments + mma, per (mt, mi) ----
        #pragma unroll
        for (int mt = 0; mt < 2; mt++) {
            #pragma unroll
            for (int mi = 0; mi < 2; mi++) {
                const float* xp = x + (size_t)(mbase + mt * 64 + wm * 32 +
                                               mi * 16 + g) * F_ + kc;
                float2 f00 = plo ? *(const float2*)xp            : make_float2(0.f, 0.f);
                float2 f10 = plo ? *(const float2*)(xp + 8 * F_) : make_float2(0.f, 0.f);
                float2 f01 = phi ? *(const float2*)(xp + 8)          : make_float2(0.f, 0.f);
                float2 f11 = phi ? *(const float2*)(xp + 8 * F_ + 8) : make_float2(0.f, 0.f);
                unsigned a0 = pack_bf16(f00.x, f00.y);
                unsigned a1 = pack_bf16(f10.x, f10.y);
                unsigned a2 = pack_bf16(f01.x, f01.y);
                unsigned a3 = pack_bf16(f11.x, f11.y);

                #pragma unroll
                for (int ni = 0; ni < 4; ni++) {
                    asm volatile(
                        "mma.sync.aligned.m16n8k16.row.col.f32.bf16.bf16.f32 "
                        "{%0,%1,%2,%3}, {%4,%5,%6,%7}, {%8,%9}, {%0,%1,%2,%3};\n"
                        : "+f"(c[mt][mi][ni][0]), "+f"(c[mt][mi][ni][1]),
                          "+f"(c[mt][mi][ni][2]), "+f"(c[mt][mi][ni][3])
                        : "r"(a0), "r"(a1), "r"(a2), "r"(a3),
                          "r"(bf[ni][0]), "r"(bf[ni][1]));
                }
            }
        }
    }

    // epilogue: pack bf16 pairs, store as u32
    unsigned* yw = reinterpret_cast<unsigned*>(g_ybf);
    #pragma unroll
    for (int mt = 0; mt < 2; mt++) {
        #pragma unroll
        for (int mi = 0; mi < 2; mi++) {
            int r0 = mbase + mt * 64 + wm * 32 + mi * 16 + g;
            #pragma unroll
            for (int ni = 0; ni < 4; ni++) {
                int col = n0 + wn * 32 + ni * 8 + 2 * tig;
                yw[((size_t)r0 * D_ + col) >> 1] =
                    pack_bf16(c[mt][mi][ni][0], c[mt][mi][ni][1]);
                yw[((size_t)(r0 + 8) * D_ + col) >> 1] =
                    pack_bf16(c[mt][mi][ni][2], c[mt][mi][ni][3]);
            }
        }
    }
}

// ---------------------------------------------------------------------------
// 7-tap conv, 3-level tree (short dep chain)
// ---------------------------------------------------------------------------
__device__ __forceinline__ float conv7(float base, const float* ac,
                                       float w0, float w1, float w2, float w3,
                                       float w4, float w5, float w6) {
    float u0 = fmaf(w0, ac[0], base);
    float u1 = fmaf(w2, ac[2], w1 * ac[1]);
    float u2 = fmaf(w4, ac[4], w3 * ac[3]);
    float u3 = fmaf(w6, ac[6], w5 * ac[5]);
    return (u0 + u1) + (u2 + u3);
}

// ---------------------------------------------------------------------------
// fused LIF kernel: grid (B, NCH) x 256 threads
// ---------------------------------------------------------------------------
template <bool GUARD>
__device__ __forceinline__ void lif1_main(const __nv_bfloat16* __restrict__ yp,
                                          const float* ac, float base,
                                          float& v, float& w0, float& w1,
                                          float& w2, float& w3, float& w4,
                                          float& w5, float& w6,
                                          int ts2, int tend, unsigned* smk,
                                          unsigned& locOr, int warp, int lane) {
    for (int t0 = ts2; t0 < tend; t0 += 4) {
        float nf[4];
        #pragma unroll
        for (int j = 0; j < 4; j++) {
            int t = t0 + 4 + j;
            if (GUARD)
                nf[j] = (t < T_) ? __bfloat162float(yp[(size_t)t * D_]) : 0.f;
            else
                nf[j] = __bfloat162float(yp[(size_t)t * D_]);
        }
        #pragma unroll
        for (int j = 0; j < 4; j++) {
            float acc = conv7(base, ac, w0, w1, w2, w3, w4, w5, w6);
            v = fmaf(v, 0.5f, acc);
            bool s = (v >= 1.0f);
            unsigned bal = __ballot_sync(0xffffffffu, s);
            if (s) v = 0.f;
            if (lane == 0) { smk[(t0 + j - ts2) * 8 + warp] = bal; locOr |= bal; }
            w0 = w1; w1 = w2; w2 = w3; w3 = w4; w4 = w5; w5 = w6; w6 = nf[j];
        }
    }
}

__global__ __launch_bounds__(256) void k_lif(const float* __restrict__ pw_b,
                                             const float* __restrict__ dw,
                                             const float* __restrict__ g1,
                                             const float* __restrict__ b1,
                                             const float* __restrict__ m1,
                                             const float* __restrict__ v1,
                                             const float* __restrict__ g2,
                                             const float* __restrict__ b2,
                                             const float* __restrict__ m2,
                                             const float* __restrict__ v2p,
                                             float* __restrict__ out) {
    __shared__ unsigned smk[SMT * 8];
    __shared__ unsigned s_any;

    const int b    = blockIdx.x;
    const int ch   = blockIdx.y;
    const int d    = threadIdx.x;
    const int lane = d & 31;
    const int warp = d >> 5;

    const int tstart = ch * CLEN;
    const int tend   = tstart + CLEN;
    const int ts2    = (ch == 0) ? 0 : tstart - WARM2;
    const int ts1    = (ch == 0) ? 0 : ts2 - WARM1;

    if (d == 0) s_any = 0u;

    // ---- phase 1: depthwise conv + BN1 + LIF1 ----
    {
        const float bias  = pw_b[d];
        const float scale = g1[d] * rsqrtf(v1[d] + 1e-5f);
        const float shift = b1[d] - m1[d] * scale;

        float ac[K_];
        float suma = 0.f;
        #pragma unroll
        for (int k = 0; k < K_; k++) {
            float a = dw[d * K_ + k];
            suma += a;
            ac[k] = 0.5f * scale * a;
        }
        const float base = 0.5f * (scale * bias * suma + shift);

        const __nv_bfloat16* yp = g_ybf + (size_t)b * T_ * D_ + d;

        float w0, w1, w2, w3, w4, w5, w6;
        {
            float wv[7];
            #pragma unroll
            for (int j = 0; j < 7; j++) {
                int t = ts1 - 3 + j;
                wv[j] = (t >= 0) ? __bfloat162float(yp[(size_t)t * D_]) : 0.f;
            }
            w0 = wv[0]; w1 = wv[1]; w2 = wv[2]; w3 = wv[3];
            w4 = wv[4]; w5 = wv[5]; w6 = wv[6];
        }

        float v = 0.f;
        // speculative warmup [ts1, ts2): no writes
        for (int t0 = ts1; t0 < ts2; t0 += 4) {
            float nf[4];
            #pragma unroll
            for (int j = 0; j < 4; j++)
                nf[j] = __bfloat162float(yp[(size_t)(t0 + 4 + j) * D_]);
            #pragma unroll
            for (int j = 0; j < 4; j++) {
                float acc = conv7(base, ac, w0, w1, w2, w3, w4, w5, w6);
                v = fmaf(v, 0.5f, acc);
                if (v >= 1.0f) v = 0.f;
                w0 = w1; w1 = w2; w2 = w3; w3 = w4; w4 = w5; w5 = w6; w6 = nf[j];
            }
        }

        unsigned locOr = 0u;
        if (ch == NCH - 1)
            lif1_main<true >(yp, ac, base, v, w0, w1, w2, w3, w4, w5, w6,
                             ts2, tend, smk, locOr, warp, lane);
        else
            lif1_main<false>(yp, ac, base, v, w0, w1, w2, w3, w4, w5, w6,
                             ts2, tend, smk, locOr, warp, lane);

        if (lane == 0 && locOr) atomicOr(&s_any, locOr);
    }
    __syncthreads();

    // ---- phase 2: sparse linear + BN2 + LIF2 + residual ----
    const int e = d;
    const float scale2 = g2[e] * rsqrtf(v2p[e] + 1e-5f);
    const float shift2 = b2[e] - m2[e] * scale2;

    float* op = out + (size_t)tstart * (B_ * D_) + (size_t)b * D_ + e;

    if (s_any == 0u) {
        if (shift2 < 1.0f) {
            #pragma unroll 10
            for (int j = 0; j < CLEN; ++j)
                op[(size_t)j * (B_ * D_)] = 0.f;
        } else {
            float v = 0.f;
            const float hs = 0.5f * shift2;
            for (int j = 0; j < tstart - ts2; ++j) {
                v = fmaf(v, 0.5f, hs);
                if (v >= 1.0f) v = 0.f;
            }
            #pragma unroll 10
            for (int j = 0; j < CLEN; ++j) {
                v = fmaf(v, 0.5f, hs);
                float sp = 0.f;
                if (v >= 1.0f) { sp = 1.f; v = 0.f; }
                op[(size_t)j * (B_ * D_)] = sp;
            }
        }
        return;
    }

    // slow path: spikes present in window
    const int      myw   = e >> 5;
    const unsigned mybit = 1u << (e & 31);
    float v = 0.f;

    for (int t = ts2; t < tend; ++t) {
        const int o = (t - ts2) * 8;
        uint4 p0 = *(const uint4*)&smk[o];
        uint4 p1 = *(const uint4*)&smk[o + 4];
        unsigned any = p0.x | p0.y | p0.z | p0.w | p1.x | p1.y | p1.z | p1.w;

        float acc = 0.f, res = 0.f;
        if (any) {
            unsigned wds[8] = {p0.x, p0.y, p0.z, p0.w, p1.x, p1.y, p1.z, p1.w};
            #pragma unroll
            for (int i = 0; i < 8; i++) {
                unsigned wd = wds[i];
                if (i == myw && (wd & mybit)) res = 1.f;
                while (wd) {
                    int bit = __ffs(wd) - 1;
                    wd &= wd - 1;
                    acc += g_linT[(size_t)(i * 32 + bit) * D_ + e];
                }
            }
        }

        float u = fmaf(acc, scale2, shift2);
        v = 0.5f * (v + u);
        float sp = 0.f;
        if (v >= 1.0f) { sp = 1.f; v = 0.f; }

        if (t >= tstart)
            out[((size_t)t * B_ + b) * D_ + e] = sp + res;
    }
}

// ---------------------------------------------------------------------------
// inputs: 0:x 1:pw_w 2:pw_b 3:dw_w 4:bn1_g 5:bn1_b 6:bn1_m 7:bn1_v
//         8:lin_w 9:bn2_g 10:bn2_b 11:bn2_m 12:bn2_v
// ---------------------------------------------------------------------------
extern "C" void kernel_launch(void* const* d_in, const int* in_sizes, int n_in,
                              void* d_out, int out_size) {
    const float* x    = (const float*)d_in[0];
    const float* pw_w = (const float*)d_in[1];
    const float* pw_b = (const float*)d_in[2];
    const float* dw_w = (const float*)d_in[3];
    const float* g1   = (const float*)d_in[4];
    const float* b1   = (const float*)d_in[5];
    const float* m1   = (const float*)d_in[6];
    const float* v1   = (const float*)d_in[7];
    const float* linw = (const float*)d_in[8];
    const float* g2   = (const float*)d_in[9];
    const float* b2   = (const float*)d_in[10];
    const float* m2   = (const float*)d_in[11];
    const float* v2   = (const float*)d_in[12];
    float* out = (float*)d_out;

    dim3 gg((B_ * T_) / 128, D_ / 128);   // (500, 2)
    k_gemm1<<<gg, 256>>>(x, pw_w, linw);

    dim3 gl(B_, NCH);
    k_lif<<<gl, 256>>>(pw_b, dw_w, g1, b1, m1, v1, g2, b2, m2, v2, out);
}

// round 10
// speedup vs baseline: 1.2135x; 1.2135x over previous
#include <cuda_runtime.h>
#include <cuda_bf16.h>
#include <cstdint>

// ---------------------------------------------------------------------------
// SEE block on GB300 — split architecture (R4 GEMM restored + targeted cuts).
// k_prep : transpose lin_w, pack pw_w -> bf16 frag-ready.
// k_gemm1: bf16 mma.sync, BM=128 BN=128, reg-prefetch double buffer,
//          B staged as uint4 copies from prepacked bf16, y stored bf16.
// k_lif  : depthwise conv+BN+LIF1 (MLP=4) -> masks in smem -> sparse linear
//          +BN+LIF2+residual; block-wide zero fast path with STG.128.
// B=64, T=1000, F=140, D=256, K=7, tau=2, v_th=1, hard reset.
// ---------------------------------------------------------------------------

#define B_    64
#define T_    1000
#define F_    140
#define D_    256
#define K_    7
#define NCH   10
#define CLEN  100
#define WARM1 16
#define WARM2 16
#define SMT   (CLEN + WARM2)
#define ASTR  12

__device__ __nv_bfloat16 g_ybf[(size_t)B_ * T_ * D_];  // GEMM out (B,T,D) bf16
__device__ unsigned      g_wbf[9 * 256 * 8];           // pw_w bf16 frag-ready
__device__ float         g_linT[D_ * D_];              // lin_w^T [d][e]

__device__ __forceinline__ unsigned pack_bf16(float lo, float hi) {
    __nv_bfloat162 h = __floats2bfloat162_rn(lo, hi);
    return *reinterpret_cast<unsigned*>(&h);
}

// ---------------------------------------------------------------------------
// prep: transpose lin_w; pack pw_w into bf16 per-k-step fragments
// ---------------------------------------------------------------------------
__global__ void k_prep(const float* __restrict__ linw,
                       const float* __restrict__ w) {
    int d = blockIdx.x, e = threadIdx.x;
    g_linT[d * D_ + e] = linw[e * D_ + d];
    if (d < 9) {
        #pragma unroll
        for (int j = 0; j < 8; j++) {
            int k = d * 16 + 2 * j;
            float lo = (k     < F_) ? w[e * F_ + k]     : 0.f;
            float hi = (k + 1 < F_) ? w[e * F_ + k + 1] : 0.f;
            g_wbf[(d * 256 + e) * 8 + j] = pack_bf16(lo, hi);
        }
    }
}

// ---------------------------------------------------------------------------
// GEMM1: y[m,n] = x[m,:].pw_w[n,:], M=64000 N=256 K=140, BM=128 BN=128.
// 8 warps (wm{0,1} x wn{0..3}), 9 k-steps, 1 sync/step, double buffer.
// ---------------------------------------------------------------------------
__global__ __launch_bounds__(256) void k_gemm1(const float* __restrict__ x) {
    __shared__ __align__(16) unsigned As[2][128 * ASTR];
    __shared__ __align__(16) unsigned Bs[2][128 * ASTR];

    const int tid = threadIdx.x;
    const int m0  = blockIdx.x * 128;
    const int n0  = blockIdx.y * 128;

    const int warp = tid >> 5, lane = tid & 31;
    const int wm   = warp >> 2;
    const int wn   = warp & 3;
    const int g    = lane >> 2, tig = lane & 3;

    const int ar0 = tid >> 2, ar1 = (tid + 256) >> 2, aq = tid & 3;
    const int brow = tid >> 1, bhalf = tid & 1;

    float4 pa0, pa1;
    uint4  pbv;

    auto ld_tiles = [&](int s) {
        const int k = s * 16 + aq * 4;
        pa0 = (k < F_) ? *(const float4*)&x[(size_t)(m0 + ar0) * F_ + k]
                       : make_float4(0.f, 0.f, 0.f, 0.f);
        pa1 = (k < F_) ? *(const float4*)&x[(size_t)(m0 + ar1) * F_ + k]
                       : make_float4(0.f, 0.f, 0.f, 0.f);
        pbv = *(const uint4*)&g_wbf[((size_t)s * 256 + n0 + brow) * 8 + bhalf * 4];
    };
    auto st_tiles = [&](int buf) {
        As[buf][ar0 * ASTR + aq * 2]     = pack_bf16(pa0.x, pa0.y);
        As[buf][ar0 * ASTR + aq * 2 + 1] = pack_bf16(pa0.z, pa0.w);
        As[buf][ar1 * ASTR + aq * 2]     = pack_bf16(pa1.x, pa1.y);
        As[buf][ar1 * ASTR + aq * 2 + 1] = pack_bf16(pa1.z, pa1.w);
        *(uint4*)&Bs[buf][brow * ASTR + bhalf * 4] = pbv;
    };

    float c[4][4][4];
    #pragma unroll
    for (int i = 0; i < 4; i++)
        #pragma unroll
        for (int j = 0; j < 4; j++)
            #pragma unroll
            for (int r = 0; r < 4; r++) c[i][j][r] = 0.f;

    ld_tiles(0);
    st_tiles(0);
    __syncthreads();

    int p = 0;
    for (int s = 0; s < 9; ++s) {
        if (s < 8) ld_tiles(s + 1);

        unsigned a[4][4], bf[4][2];
        #pragma unroll
        for (int mi = 0; mi < 4; mi++) {
            int r = wm * 64 + mi * 16;
            a[mi][0] = As[p][(r + g) * ASTR + tig];
            a[mi][1] = As[p][(r + g + 8) * ASTR + tig];
            a[mi][2] = As[p][(r + g) * ASTR + tig + 4];
            a[mi][3] = As[p][(r + g + 8) * ASTR + tig + 4];
        }
        #pragma unroll
        for (int ni = 0; ni < 4; ni++) {
            int cb = wn * 32 + ni * 8;
            bf[ni][0] = Bs[p][(cb + g) * ASTR + tig];
            bf[ni][1] = Bs[p][(cb + g) * ASTR + tig + 4];
        }
        #pragma unroll
        for (int mi = 0; mi < 4; mi++)
            #pragma unroll
            for (int ni = 0; ni < 4; ni++) {
                asm volatile(
                    "mma.sync.aligned.m16n8k16.row.col.f32.bf16.bf16.f32 "
                    "{%0,%1,%2,%3}, {%4,%5,%6,%7}, {%8,%9}, {%0,%1,%2,%3};\n"
                    : "+f"(c[mi][ni][0]), "+f"(c[mi][ni][1]),
                      "+f"(c[mi][ni][2]), "+f"(c[mi][ni][3])
                    : "r"(a[mi][0]), "r"(a[mi][1]), "r"(a[mi][2]), "r"(a[mi][3]),
                      "r"(bf[ni][0]), "r"(bf[ni][1]));
            }

        if (s < 8) st_tiles(1 - p);
        __syncthreads();
        p ^= 1;
    }

    // epilogue: pack bf16 pairs, store as u32
    unsigned* yw = reinterpret_cast<unsigned*>(g_ybf);
    #pragma unroll
    for (int mi = 0; mi < 4; mi++) {
        int r0 = m0 + wm * 64 + mi * 16 + g;
        #pragma unroll
        for (int ni = 0; ni < 4; ni++) {
            int col = n0 + wn * 32 + ni * 8 + 2 * tig;
            yw[((size_t)r0 * D_ + col) >> 1] =
                pack_bf16(c[mi][ni][0], c[mi][ni][1]);
            yw[((size_t)(r0 + 8) * D_ + col) >> 1] =
                pack_bf16(c[mi][ni][2], c[mi][ni][3]);
        }
    }
}

// ---------------------------------------------------------------------------
// fused LIF kernel: grid (B, NCH) x 256 threads
// ---------------------------------------------------------------------------
template <bool GUARD>
__device__ __forceinline__ void lif1_main(const __nv_bfloat16* __restrict__ yp,
                                          const float* ac, float base,
                                          float& v, float& w0, float& w1,
                                          float& w2, float& w3, float& w4,
                                          float& w5, float& w6,
                                          int ts2, int tend, unsigned* smk,
                                          unsigned& locOr, int warp, int lane) {
    for (int t0 = ts2; t0 < tend; t0 += 4) {
        float nf[4];
        #pragma unroll
        for (int j = 0; j < 4; j++) {
            int t = t0 + 4 + j;
            if (GUARD)
                nf[j] = (t < T_) ? __bfloat162float(yp[(size_t)t * D_]) : 0.f;
            else
                nf[j] = __bfloat162float(yp[(size_t)t * D_]);
        }
        #pragma unroll
        for (int j = 0; j < 4; j++) {
            float acc = base;
            acc = fmaf(w0, ac[0], acc); acc = fmaf(w1, ac[1], acc);
            acc = fmaf(w2, ac[2], acc); acc = fmaf(w3, ac[3], acc);
            acc = fmaf(w4, ac[4], acc); acc = fmaf(w5, ac[5], acc);
            acc = fmaf(w6, ac[6], acc);
            v = fmaf(v, 0.5f, acc);
            bool s = (v >= 1.0f);
            unsigned bal = __ballot_sync(0xffffffffu, s);
            if (s) v = 0.f;
            if (lane == 0) { smk[(t0 + j - ts2) * 8 + warp] = bal; locOr |= bal; }
            w0 = w1; w1 = w2; w2 = w3; w3 = w4; w4 = w5; w5 = w6; w6 = nf[j];
        }
    }
}

__global__ __launch_bounds__(256) void k_lif(const float* __restrict__ pw_b,
                                             const float* __restrict__ dw,
                                             const float* __restrict__ g1,
                                             const float* __restrict__ b1,
                                             const float* __restrict__ m1,
                                             const float* __restrict__ v1,
                                             const float* __restrict__ g2,
                                             const float* __restrict__ b2,
                                             const float* __restrict__ m2,
                                             const float* __restrict__ v2p,
                                             float* __restrict__ out) {
    __shared__ unsigned smk[SMT * 8];
    __shared__ unsigned s_any;     // spikes anywhere in window
    __shared__ unsigned s_hot;     // any channel with BN2 fixpoint >= 1

    const int b    = blockIdx.x;
    const int ch   = blockIdx.y;
    const int d    = threadIdx.x;
    const int lane = d & 31;
    const int warp = d >> 5;

    const int tstart = ch * CLEN;
    const int tend   = tstart + CLEN;
    const int ts2    = (ch == 0) ? 0 : tstart - WARM2;
    const int ts1    = (ch == 0) ? 0 : ts2 - WARM1;

    if (d == 0) { s_any = 0u; s_hot = 0u; }

    // BN2 constants + hot flag (needed before fast-path decision)
    const float scale2 = g2[d] * rsqrtf(v2p[d] + 1e-5f);
    const float shift2 = b2[d] - m2[d] * scale2;
    {
        unsigned hot = __ballot_sync(0xffffffffu, shift2 >= 1.0f);
        if (lane == 0 && hot) atomicOr(&s_hot, hot);
    }

    // ---- phase 1: depthwise conv + BN1 + LIF1 ----
    {
        const float bias  = pw_b[d];
        const float scale = g1[d] * rsqrtf(v1[d] + 1e-5f);
        const float shift = b1[d] - m1[d] * scale;

        float ac[K_];
        float suma = 0.f;
        #pragma unroll
        for (int k = 0; k < K_; k++) {
            float a = dw[d * K_ + k];
            suma += a;
            ac[k] = 0.5f * scale * a;
        }
        const float base = 0.5f * (scale * bias * suma + shift);

        const __nv_bfloat16* yp = g_ybf + (size_t)b * T_ * D_ + d;

        float w0, w1, w2, w3, w4, w5, w6;
        {
            float wv[7];
            #pragma unroll
            for (int j = 0; j < 7; j++) {
                int t = ts1 - 3 + j;
                wv[j] = (t >= 0) ? __bfloat162float(yp[(size_t)t * D_]) : 0.f;
            }
            w0 = wv[0]; w1 = wv[1]; w2 = wv[2]; w3 = wv[3];
            w4 = wv[4]; w5 = wv[5]; w6 = wv[6];
        }

        float v = 0.f;
        for (int t0 = ts1; t0 < ts2; t0 += 4) {
            float nf[4];
            #pragma unroll
            for (int j = 0; j < 4; j++)
                nf[j] = __bfloat162float(yp[(size_t)(t0 + 4 + j) * D_]);
            #pragma unroll
            for (int j = 0; j < 4; j++) {
                float acc = base;
                acc = fmaf(w0, ac[0], acc); acc = fmaf(w1, ac[1], acc);
                acc = fmaf(w2, ac[2], acc); acc = fmaf(w3, ac[3], acc);
                acc = fmaf(w4, ac[4], acc); acc = fmaf(w5, ac[5], acc);
                acc = fmaf(w6, ac[6], acc);
                v = fmaf(v, 0.5f, acc);
                if (v >= 1.0f) v = 0.f;
                w0 = w1; w1 = w2; w2 = w3; w3 = w4; w4 = w5; w5 = w6; w6 = nf[j];
            }
        }

        unsigned locOr = 0u;
        if (ch == NCH - 1)
            lif1_main<true >(yp, ac, base, v, w0, w1, w2, w3, w4, w5, w6,
                             ts2, tend, smk, locOr, warp, lane);
        else
            lif1_main<false>(yp, ac, base, v, w0, w1, w2, w3, w4, w5, w6,
                             ts2, tend, smk, locOr, warp, lane);

        if (lane == 0 && locOr) atomicOr(&s_any, locOr);
    }
    __syncthreads();

    // ---- phase 2: sparse linear + BN2 + LIF2 + residual ----
    if (s_any == 0u) {
        if (s_hot == 0u) {
            // whole chunk provably zero: vectorized block-cooperative store
            float4* ob = (float4*)(out + (size_t)tstart * (B_ * D_) +
                                   (size_t)b * D_) + (d & 63);
            const int tof = d >> 6;                 // 0..3
            const float4 z = make_float4(0.f, 0.f, 0.f, 0.f);
            #pragma unroll
            for (int jj = 0; jj < CLEN / 4; ++jj)
                ob[(size_t)(jj * 4 + tof) * (B_ * D_ / 4)] = z;
        } else {
            // constant drive per channel (rare)
            float* op = out + (size_t)tstart * (B_ * D_) + (size_t)b * D_ + d;
            if (shift2 < 1.0f) {
                #pragma unroll 10
                for (int j = 0; j < CLEN; ++j)
                    op[(size_t)j * (B_ * D_)] = 0.f;
            } else {
                float v = 0.f;
                const float hs = 0.5f * shift2;
                for (int j = 0; j < tstart - ts2; ++j) {
                    v = fmaf(v, 0.5f, hs);
                    if (v >= 1.0f) v = 0.f;
                }
                #pragma unroll 10
                for (int j = 0; j < CLEN; ++j) {
                    v = fmaf(v, 0.5f, hs);
                    float sp = 0.f;
                    if (v >= 1.0f) { sp = 1.f; v = 0.f; }
                    op[(size_t)j * (B_ * D_)] = sp;
                }
            }
        }
        return;
    }

    // slow path: spikes present in window
    const int e = d;
    const int      myw   = e >> 5;
    const unsigned mybit = 1u << (e & 31);
    float v = 0.f;

    for (int t = ts2; t < tend; ++t) {
        const int o = (t - ts2) * 8;
        uint4 p0 = *(const uint4*)&smk[o];
        uint4 p1 = *(const uint4*)&smk[o + 4];
        unsigned any = p0.x | p0.y | p0.z | p0.w | p1.x | p1.y | p1.z | p1.w;

        float acc = 0.f, res = 0.f;
        if (any) {
            unsigned wds[8] = {p0.x, p0.y, p0.z, p0.w, p1.x, p1.y, p1.z, p1.w};
            #pragma unroll
            for (int i = 0; i < 8; i++) {
                unsigned wd = wds[i];
                if (i == myw && (wd & mybit)) res = 1.f;
                while (wd) {
                    int bit = __ffs(wd) - 1;
                    wd &= wd - 1;
                    acc += g_linT[(size_t)(i * 32 + bit) * D_ + e];
                }
            }
        }

        float u = fmaf(acc, scale2, shift2);
        v = 0.5f * (v + u);
        float sp = 0.f;
        if (v >= 1.0f) { sp = 1.f; v = 0.f; }

        if (t >= tstart)
            out[((size_t)t * B_ + b) * D_ + e] = sp + res;
    }
}

// ---------------------------------------------------------------------------
// inputs: 0:x 1:pw_w 2:pw_b 3:dw_w 4:bn1_g 5:bn1_b 6:bn1_m 7:bn1_v
//         8:lin_w 9:bn2_g 10:bn2_b 11:bn2_m 12:bn2_v
// ---------------------------------------------------------------------------
extern "C" void kernel_launch(void* const* d_in, const int* in_sizes, int n_in,
                              void* d_out, int out_size) {
    const float* x    = (const float*)d_in[0];
    const float* pw_w = (const float*)d_in[1];
    const float* pw_b = (const float*)d_in[2];
    const float* dw_w = (const float*)d_in[3];
    const float* g1   = (const float*)d_in[4];
    const float* b1   = (const float*)d_in[5];
    const float* m1   = (const float*)d_in[6];
    const float* v1   = (const float*)d_in[7];
    const float* linw = (const float*)d_in[8];
    const float* g2   = (const float*)d_in[9];
    const float* b2   = (const float*)d_in[10];
    const float* m2   = (const float*)d_in[11];
    const float* v2   = (const float*)d_in[12];
    float* out = (float*)d_out;

    k_prep<<<D_, D_>>>(linw, pw_w);

    dim3 gg((B_ * T_) / 128, D_ / 128);   // (500, 2)
    k_gemm1<<<gg, 256>>>(x);

    dim3 gl(B_, NCH);
    k_lif<<<gl, 256>>>(pw_b, dw_w, g1, b1, m1, v1, g2, b2, m2, v2, out);
}

// round 13
// speedup vs baseline: 1.2489x; 1.0292x over previous
#include <cuda_runtime.h>
#include <cuda_bf16.h>
#include <cstdint>

// ---------------------------------------------------------------------------
// SEE block on GB300 — split architecture (R10 + ldmatrix + folded transpose).
// k_prep : pack pw_w -> bf16 frag-ready (tiny).
// k_gemm1: bf16 mma.sync, BM=128 BN=128, reg-prefetch double buffer,
//          fragments via ldmatrix.x4 (per-step buffers, NO s-offset);
//          first 64 blocks also do a tiled transpose of lin_w. y -> bf16.
// k_lif  : depthwise conv+BN+LIF1 -> masks in smem -> sparse linear+BN+LIF2
//          +residual; block-wide zero fast path (unchanged).
// B=64, T=1000, F=140, D=256, K=7, tau=2, v_th=1, hard reset.
// ---------------------------------------------------------------------------

#define B_    64
#define T_    1000
#define F_    140
#define D_    256
#define K_    7
#define NCH   10
#define CLEN  100
#define WARM1 16
#define WARM2 16
#define SMT   (CLEN + WARM2)
#define ASTR  12

__device__ __nv_bfloat16 g_ybf[(size_t)B_ * T_ * D_];  // GEMM out (B,T,D) bf16
__device__ unsigned      g_wbf[9 * 256 * 8];           // pw_w bf16 frag-ready
__device__ float         g_linT[D_ * D_];              // lin_w^T [d][e]

__device__ __forceinline__ unsigned pack_bf16(float lo, float hi) {
    __nv_bfloat162 h = __floats2bfloat162_rn(lo, hi);
    return *reinterpret_cast<unsigned*>(&h);
}

__device__ __forceinline__ uint32_t smem_u32(const void* p) {
    uint32_t a;
    asm("{ .reg .u64 t; cvta.to.shared.u64 t, %1; cvt.u32.u64 %0, t; }"
        : "=r"(a) : "l"(p));
    return a;
}

#define LDSM_X4(r0, r1, r2, r3, addr)                                         \
    asm volatile("ldmatrix.sync.aligned.m8n8.x4.shared.b16 {%0,%1,%2,%3}, [%4];" \
        : "=r"(r0), "=r"(r1), "=r"(r2), "=r"(r3) : "r"(addr))

// ---------------------------------------------------------------------------
// prep: pack pw_w into bf16 per-k-step fragments. grid 9 x 256.
// ---------------------------------------------------------------------------
__global__ void k_prep(const float* __restrict__ w) {
    int s = blockIdx.x, e = threadIdx.x;
    #pragma unroll
    for (int j = 0; j < 8; j++) {
        int k = s * 16 + 2 * j;
        float lo = (k     < F_) ? w[e * F_ + k]     : 0.f;
        float hi = (k + 1 < F_) ? w[e * F_ + k + 1] : 0.f;
        g_wbf[(s * 256 + e) * 8 + j] = pack_bf16(lo, hi);
    }
}

// ---------------------------------------------------------------------------
// GEMM1: y[m,n] = x[m,:].pw_w[n,:], M=64000 N=256 K=140, BM=128 BN=128.
// 8 warps (wm{0,1} x wn{0..3}), 9 k-steps, 1 sync/step, double buffer.
// Fragments via ldmatrix. Blocks (x<64, y==0) fold the lin_w transpose.
// ---------------------------------------------------------------------------
__global__ __launch_bounds__(256) void k_gemm1(const float* __restrict__ x,
                                               const float* __restrict__ linw) {
    __shared__ __align__(16) unsigned As[2][128 * ASTR];
    __shared__ __align__(16) unsigned Bs[2][128 * ASTR];

    const int tid = threadIdx.x;
    const int m0  = blockIdx.x * 128;
    const int n0  = blockIdx.y * 128;

    // folded TILED transpose of lin_w (first 64 blocks of y==0 slice),
    // using As[0] as scratch (32x33 floats = 4224 B < 6144 B) before staging.
    if (blockIdx.y == 0 && blockIdx.x < 64) {
        float* ts = reinterpret_cast<float*>(&As[0][0]);
        const int bi = blockIdx.x & 7, bj = blockIdx.x >> 3;
        const int tx = tid & 31, ty0 = tid >> 5;
        #pragma unroll
        for (int r = 0; r < 4; r++) {
            int ty = ty0 + 8 * r;
            ts[ty * 33 + tx] = linw[(size_t)(bj * 32 + ty) * D_ + bi * 32 + tx];
        }
        __syncthreads();
        #pragma unroll
        for (int r = 0; r < 4; r++) {
            int ty = ty0 + 8 * r;
            g_linT[(size_t)(bi * 32 + ty) * D_ + bj * 32 + tx] = ts[tx * 33 + ty];
        }
        __syncthreads();
    }

    const int warp = tid >> 5, lane = tid & 31;
    const int wm   = warp >> 2;
    const int wn   = warp & 3;
    const int g    = lane >> 2, tig = lane & 3;

    const int ar0 = tid >> 2, ar1 = (tid + 256) >> 2, aq = tid & 3;
    const int brow = tid >> 1, bhalf = tid & 1;

    float4 pa0, pa1;
    uint4  pbv;

    auto ld_tiles = [&](int s) {
        const int k = s * 16 + aq * 4;
        pa0 = (k < F_) ? *(const float4*)&x[(size_t)(m0 + ar0) * F_ + k]
                       : make_float4(0.f, 0.f, 0.f, 0.f);
        pa1 = (k < F_) ? *(const float4*)&x[(size_t)(m0 + ar1) * F_ + k]
                       : make_float4(0.f, 0.f, 0.f, 0.f);
        pbv = *(const uint4*)&g_wbf[((size_t)s * 256 + n0 + brow) * 8 + bhalf * 4];
    };
    auto st_tiles = [&](int buf) {
        As[buf][ar0 * ASTR + aq * 2]     = pack_bf16(pa0.x, pa0.y);
        As[buf][ar0 * ASTR + aq * 2 + 1] = pack_bf16(pa0.z, pa0.w);
        As[buf][ar1 * ASTR + aq * 2]     = pack_bf16(pa1.x, pa1.y);
        As[buf][ar1 * ASTR + aq * 2 + 1] = pack_bf16(pa1.z, pa1.w);
        *(uint4*)&Bs[buf][brow * ASTR + bhalf * 4] = pbv;
    };

    // ldmatrix per-lane address offsets (bytes); each buffer = ONE k-step,
    // so the offset is constant across steps (parity p selects the buffer).
    const unsigned asu[2] = { smem_u32(&As[0][0]), smem_u32(&As[1][0]) };
    const unsigned bsu[2] = { smem_u32(&Bs[0][0]), smem_u32(&Bs[1][0]) };
    unsigned aOff[4], bOff[2];
    #pragma unroll
    for (int mi = 0; mi < 4; mi++)
        aOff[mi] = (unsigned)((wm * 64 + mi * 16 + (lane & 15)) * (ASTR * 4) +
                              ((lane & 16) ? 16 : 0));
    #pragma unroll
    for (int nj = 0; nj < 2; nj++)
        bOff[nj] = (unsigned)((wn * 32 + nj * 16 + ((lane >> 4) & 1) * 8 +
                               (lane & 7)) * (ASTR * 4) +
                              ((lane & 8) ? 16 : 0));

    float c[4][4][4];
    #pragma unroll
    for (int i = 0; i < 4; i++)
        #pragma unroll
        for (int j = 0; j < 4; j++)
            #pragma unroll
            for (int r = 0; r < 4; r++) c[i][j][r] = 0.f;

    ld_tiles(0);
    st_tiles(0);
    __syncthreads();

    int p = 0;
    for (int s = 0; s < 9; ++s) {
        if (s < 8) ld_tiles(s + 1);

        unsigned a[4][4], bf[4][2];
        #pragma unroll
        for (int mi = 0; mi < 4; mi++)
            LDSM_X4(a[mi][0], a[mi][1], a[mi][2], a[mi][3],
                    asu[p] + aOff[mi]);
        #pragma unroll
        for (int nj = 0; nj < 2; nj++)
            LDSM_X4(bf[2 * nj][0], bf[2 * nj][1], bf[2 * nj + 1][0],
                    bf[2 * nj + 1][1], bsu[p] + bOff[nj]);

        #pragma unroll
        for (int mi = 0; mi < 4; mi++)
            #pragma unroll
            for (int ni = 0; ni < 4; ni++) {
                asm volatile(
                    "mma.sync.aligned.m16n8k16.row.col.f32.bf16.bf16.f32 "
                    "{%0,%1,%2,%3}, {%4,%5,%6,%7}, {%8,%9}, {%0,%1,%2,%3};\n"
                    : "+f"(c[mi][ni][0]), "+f"(c[mi][ni][1]),
                      "+f"(c[mi][ni][2]), "+f"(c[mi][ni][3])
                    : "r"(a[mi][0]), "r"(a[mi][1]), "r"(a[mi][2]), "r"(a[mi][3]),
                      "r"(bf[ni][0]), "r"(bf[ni][1]));
            }

        if (s < 8) st_tiles(1 - p);
        __syncthreads();
        p ^= 1;
    }

    // epilogue: pack bf16 pairs, store as u32
    unsigned* yw = reinterpret_cast<unsigned*>(g_ybf);
    #pragma unroll
    for (int mi = 0; mi < 4; mi++) {
        int r0 = m0 + wm * 64 + mi * 16 + g;
        #pragma unroll
        for (int ni = 0; ni < 4; ni++) {
            int col = n0 + wn * 32 + ni * 8 + 2 * tig;
            yw[((size_t)r0 * D_ + col) >> 1] =
                pack_bf16(c[mi][ni][0], c[mi][ni][1]);
            yw[((size_t)(r0 + 8) * D_ + col) >> 1] =
                pack_bf16(c[mi][ni][2], c[mi][ni][3]);
        }
    }
}

// ---------------------------------------------------------------------------
// fused LIF kernel: grid (B, NCH) x 256 threads (unchanged from R10)
// ---------------------------------------------------------------------------
template <bool GUARD>
__device__ __forceinline__ void lif1_main(const __nv_bfloat16* __restrict__ yp,
                                          const float* ac, float base,
                                          float& v, float& w0, float& w1,
                                          float& w2, float& w3, float& w4,
                                          float& w5, float& w6,
                                          int ts2, int tend, unsigned* smk,
                                          unsigned& locOr, int warp, int lane) {
    for (int t0 = ts2; t0 < tend; t0 += 4) {
        float nf[4];
        #pragma unroll
        for (int j = 0; j < 4; j++) {
            int t = t0 + 4 + j;
            if (GUARD)
                nf[j] = (t < T_) ? __bfloat162float(yp[(size_t)t * D_]) : 0.f;
            else
                nf[j] = __bfloat162float(yp[(size_t)t * D_]);
        }
        #pragma unroll
        for (int j = 0; j < 4; j++) {
            float acc = base;
            acc = fmaf(w0, ac[0], acc); acc = fmaf(w1, ac[1], acc);
            acc = fmaf(w2, ac[2], acc); acc = fmaf(w3, ac[3], acc);
            acc = fmaf(w4, ac[4], acc); acc = fmaf(w5, ac[5], acc);
            acc = fmaf(w6, ac[6], acc);
            v = fmaf(v, 0.5f, acc);
            bool s = (v >= 1.0f);
            unsigned bal = __ballot_sync(0xffffffffu, s);
            if (s) v = 0.f;
            if (lane == 0) { smk[(t0 + j - ts2) * 8 + warp] = bal; locOr |= bal; }
            w0 = w1; w1 = w2; w2 = w3; w3 = w4; w4 = w5; w5 = w6; w6 = nf[j];
        }
    }
}

__global__ __launch_bounds__(256) void k_lif(const float* __restrict__ pw_b,
                                             const float* __restrict__ dw,
                                             const float* __restrict__ g1,
                                             const float* __restrict__ b1,
                                             const float* __restrict__ m1,
                                             const float* __restrict__ v1,
                                             const float* __restrict__ g2,
                                             const float* __restrict__ b2,
                                             const float* __restrict__ m2,
                                             const float* __restrict__ v2p,
                                             float* __restrict__ out) {
    __shared__ unsigned smk[SMT * 8];
    __shared__ unsigned s_any;
    __shared__ unsigned s_hot;

    const int b    = blockIdx.x;
    const int ch   = blockIdx.y;
    const int d    = threadIdx.x;
    const int lane = d & 31;
    const int warp = d >> 5;

    const int tstart = ch * CLEN;
    const int tend   = tstart + CLEN;
    const int ts2    = (ch == 0) ? 0 : tstart - WARM2;
    const int ts1    = (ch == 0) ? 0 : ts2 - WARM1;

    if (d == 0) { s_any = 0u; s_hot = 0u; }

    const float scale2 = g2[d] * rsqrtf(v2p[d] + 1e-5f);
    const float shift2 = b2[d] - m2[d] * scale2;
    {
        unsigned hot = __ballot_sync(0xffffffffu, shift2 >= 1.0f);
        if (lane == 0 && hot) atomicOr(&s_hot, hot);
    }

    // ---- phase 1: depthwise conv + BN1 + LIF1 ----
    {
        const float bias  = pw_b[d];
        const float scale = g1[d] * rsqrtf(v1[d] + 1e-5f);
        const float shift = b1[d] - m1[d] * scale;

        float ac[K_];
        float suma = 0.f;
        #pragma unroll
        for (int k = 0; k < K_; k++) {
            float a = dw[d * K_ + k];
            suma += a;
            ac[k] = 0.5f * scale * a;
        }
        const float base = 0.5f * (scale * bias * suma + shift);

        const __nv_bfloat16* yp = g_ybf + (size_t)b * T_ * D_ + d;

        float w0, w1, w2, w3, w4, w5, w6;
        {
            float wv[7];
            #pragma unroll
            for (int j = 0; j < 7; j++) {
                int t = ts1 - 3 + j;
                wv[j] = (t >= 0) ? __bfloat162float(yp[(size_t)t * D_]) : 0.f;
            }
            w0 = wv[0]; w1 = wv[1]; w2 = wv[2]; w3 = wv[3];
            w4 = wv[4]; w5 = wv[5]; w6 = wv[6];
        }

        float v = 0.f;
        for (int t0 = ts1; t0 < ts2; t0 += 4) {
            float nf[4];
            #pragma unroll
            for (int j = 0; j < 4; j++)
                nf[j] = __bfloat162float(yp[(size_t)(t0 + 4 + j) * D_]);
            #pragma unroll
            for (int j = 0; j < 4; j++) {
                float acc = base;
                acc = fmaf(w0, ac[0], acc); acc = fmaf(w1, ac[1], acc);
                acc = fmaf(w2, ac[2], acc); acc = fmaf(w3, ac[3], acc);
                acc = fmaf(w4, ac[4], acc); acc = fmaf(w5, ac[5], acc);
                acc = fmaf(w6, ac[6], acc);
                v = fmaf(v, 0.5f, acc);
                if (v >= 1.0f) v = 0.f;
                w0 = w1; w1 = w2; w2 = w3; w3 = w4; w4 = w5; w5 = w6; w6 = nf[j];
            }
        }

        unsigned locOr = 0u;
        if (ch == NCH - 1)
            lif1_main<true >(yp, ac, base, v, w0, w1, w2, w3, w4, w5, w6,
                             ts2, tend, smk, locOr, warp, lane);
        else
            lif1_main<false>(yp, ac, base, v, w0, w1, w2, w3, w4, w5, w6,
                             ts2, tend, smk, locOr, warp, lane);

        if (lane == 0 && locOr) atomicOr(&s_any, locOr);
    }
    __syncthreads();

    // ---- phase 2: sparse linear + BN2 + LIF2 + residual ----
    if (s_any == 0u) {
        if (s_hot == 0u) {
            float4* ob = (float4*)(out + (size_t)tstart * (B_ * D_) +
                                   (size_t)b * D_) + (d & 63);
            const int tof = d >> 6;
            const float4 z = make_float4(0.f, 0.f, 0.f, 0.f);
            #pragma unroll
            for (int jj = 0; jj < CLEN / 4; ++jj)
                ob[(size_t)(jj * 4 + tof) * (B_ * D_ / 4)] = z;
        } else {
            float* op = out + (size_t)tstart * (B_ * D_) + (size_t)b * D_ + d;
            if (shift2 < 1.0f) {
                #pragma unroll 10
                for (int j = 0; j < CLEN; ++j)
                    op[(size_t)j * (B_ * D_)] = 0.f;
            } else {
                float v = 0.f;
                const float hs = 0.5f * shift2;
                for (int j = 0; j < tstart - ts2; ++j) {
                    v = fmaf(v, 0.5f, hs);
                    if (v >= 1.0f) v = 0.f;
                }
                #pragma unroll 10
                for (int j = 0; j < CLEN; ++j) {
                    v = fmaf(v, 0.5f, hs);
                    float sp = 0.f;
                    if (v >= 1.0f) { sp = 1.f; v = 0.f; }
                    op[(size_t)j * (B_ * D_)] = sp;
                }
            }
        }
        return;
    }

    // slow path: spikes present in window
    const int e = d;
    const int      myw   = e >> 5;
    const unsigned mybit = 1u << (e & 31);
    float v = 0.f;

    for (int t = ts2; t < tend; ++t) {
        const int o = (t - ts2) * 8;
        uint4 p0 = *(const uint4*)&smk[o];
        uint4 p1 = *(const uint4*)&smk[o + 4];
        unsigned any = p0.x | p0.y | p0.z | p0.w | p1.x | p1.y | p1.z | p1.w;

        float acc = 0.f, res = 0.f;
        if (any) {
            unsigned wds[8] = {p0.x, p0.y, p0.z, p0.w, p1.x, p1.y, p1.z, p1.w};
            #pragma unroll
            for (int i = 0; i < 8; i++) {
                unsigned wd = wds[i];
                if (i == myw && (wd & mybit)) res = 1.f;
                while (wd) {
                    int bit = __ffs(wd) - 1;
                    wd &= wd - 1;
                    acc += g_linT[(size_t)(i * 32 + bit) * D_ + e];
                }
            }
        }

        float u = fmaf(acc, scale2, shift2);
        v = 0.5f * (v + u);
        float sp = 0.f;
        if (v >= 1.0f) { sp = 1.f; v = 0.f; }

        if (t >= tstart)
            out[((size_t)t * B_ + b) * D_ + e] = sp + res;
    }
}

// ---------------------------------------------------------------------------
// inputs: 0:x 1:pw_w 2:pw_b 3:dw_w 4:bn1_g 5:bn1_b 6:bn1_m 7:bn1_v
//         8:lin_w 9:bn2_g 10:bn2_b 11:bn2_m 12:bn2_v
// ---------------------------------------------------------------------------
extern "C" void kernel_launch(void* const* d_in, const int* in_sizes, int n_in,
                              void* d_out, int out_size) {
    const float* x    = (const float*)d_in[0];
    const float* pw_w = (const float*)d_in[1];
    const float* pw_b = (const float*)d_in[2];
    const float* dw_w = (const float*)d_in[3];
    const float* g1   = (const float*)d_in[4];
    const float* b1   = (const float*)d_in[5];
    const float* m1   = (const float*)d_in[6];
    const float* v1   = (const float*)d_in[7];
    const float* linw = (const float*)d_in[8];
    const float* g2   = (const float*)d_in[9];
    const float* b2   = (const float*)d_in[10];
    const float* m2   = (const float*)d_in[11];
    const float* v2   = (const float*)d_in[12];
    float* out = (float*)d_out;

    k_prep<<<9, 256>>>(pw_w);

    dim3 gg((B_ * T_) / 128, D_ / 128);   // (500, 2)
    k_gemm1<<<gg, 256>>>(x, linw);

    dim3 gl(B_, NCH);
    k_lif<<<gl, 256>>>(pw_b, dw_w, g1, b1, m1, v1, g2, b2, m2, v2, out);
}

// round 14
// speedup vs baseline: 1.3151x; 1.0530x over previous
#include <cuda_runtime.h>
#include <cuda_bf16.h>
#include <cstdint>

// ---------------------------------------------------------------------------
// SEE block on GB300 — split architecture.
// k_prep : coalesced pack of pw_w -> bf16 frag-ready (grid 256).
// k_gemm1: bf16 mma.sync, BM=128 BN=128, ldmatrix frags, 2-step LDG
//          prefetch (two register sets, double-buffered smem); first 64
//          blocks fold a tiled transpose of lin_w. y stored bf16.
// k_lif  : depthwise conv+BN+LIF1 -> masks in smem -> sparse linear+BN+LIF2
//          +residual; block-wide zero fast path. WARM=12.
// B=64, T=1000, F=140, D=256, K=7, tau=2, v_th=1, hard reset.
// ---------------------------------------------------------------------------

#define B_    64
#define T_    1000
#define F_    140
#define D_    256
#define K_    7
#define NCH   10
#define CLEN  100
#define WARM1 12
#define WARM2 12
#define SMT   (CLEN + WARM2)
#define ASTR  12

__device__ __nv_bfloat16 g_ybf[(size_t)B_ * T_ * D_];  // GEMM out (B,T,D) bf16
__device__ unsigned      g_wbf[9 * 256 * 8];           // pw_w bf16 frag-ready
__device__ float         g_linT[D_ * D_];              // lin_w^T [d][e]

__device__ __forceinline__ unsigned pack_bf16(float lo, float hi) {
    __nv_bfloat162 h = __floats2bfloat162_rn(lo, hi);
    return *reinterpret_cast<unsigned*>(&h);
}

__device__ __forceinline__ uint32_t smem_u32(const void* p) {
    uint32_t a;
    asm("{ .reg .u64 t; cvta.to.shared.u64 t, %1; cvt.u32.u64 %0, t; }"
        : "=r"(a) : "l"(p));
    return a;
}

#define LDSM_X4(r0, r1, r2, r3, addr)                                         \
    asm volatile("ldmatrix.sync.aligned.m8n8.x4.shared.b16 {%0,%1,%2,%3}, [%4];" \
        : "=r"(r0), "=r"(r1), "=r"(r2), "=r"(r3) : "r"(addr))

// ---------------------------------------------------------------------------
// prep: coalesced pack of pw_w. grid 256 (block per row e), 160 threads.
// ---------------------------------------------------------------------------
__global__ __launch_bounds__(160) void k_prep(const float* __restrict__ w) {
    __shared__ float ws[F_];
    const int e = blockIdx.x, t = threadIdx.x;
    if (t < F_) ws[t] = w[(size_t)e * F_ + t];          // coalesced
    __syncthreads();
    if (t < 72) {
        int s = t >> 3, j = t & 7;
        int k = s * 16 + 2 * j;
        float lo = (k     < F_) ? ws[k]     : 0.f;
        float hi = (k + 1 < F_) ? ws[k + 1] : 0.f;
        g_wbf[(s * 256 + e) * 8 + j] = pack_bf16(lo, hi);
    }
}

// ---------------------------------------------------------------------------
// GEMM1: y[m,n] = x[m,:].pw_w[n,:], M=64000 N=256 K=140, BM=128 BN=128.
// 8 warps (wm{0,1} x wn{0..3}), 9 k-steps, 1 sync/step, double buffer,
// 2-step LDG prefetch. Blocks (x<64, y==0) fold the lin_w transpose.
// ---------------------------------------------------------------------------
__global__ __launch_bounds__(256) void k_gemm1(const float* __restrict__ x,
                                               const float* __restrict__ linw) {
    __shared__ __align__(16) unsigned As[2][128 * ASTR];
    __shared__ __align__(16) unsigned Bs[2][128 * ASTR];

    const int tid = threadIdx.x;
    const int m0  = blockIdx.x * 128;
    const int n0  = blockIdx.y * 128;

    // folded TILED transpose of lin_w (first 64 blocks of y==0 slice)
    if (blockIdx.y == 0 && blockIdx.x < 64) {
        float* ts = reinterpret_cast<float*>(&As[0][0]);
        const int bi = blockIdx.x & 7, bj = blockIdx.x >> 3;
        const int tx = tid & 31, ty0 = tid >> 5;
        #pragma unroll
        for (int r = 0; r < 4; r++) {
            int ty = ty0 + 8 * r;
            ts[ty * 33 + tx] = linw[(size_t)(bj * 32 + ty) * D_ + bi * 32 + tx];
        }
        __syncthreads();
        #pragma unroll
        for (int r = 0; r < 4; r++) {
            int ty = ty0 + 8 * r;
            g_linT[(size_t)(bi * 32 + ty) * D_ + bj * 32 + tx] = ts[tx * 33 + ty];
        }
        __syncthreads();
    }

    const int warp = tid >> 5, lane = tid & 31;
    const int wm   = warp >> 2;
    const int wn   = warp & 3;
    const int g    = lane >> 2, tig = lane & 3;

    const int ar0 = tid >> 2, ar1 = (tid + 256) >> 2, aq = tid & 3;
    const int brow = tid >> 1, bhalf = tid & 1;

    // two staging register sets for 2-step prefetch
    float4 pa0[2], pa1[2];
    uint4  pbv[2];

    auto ldg = [&](int s, int r) {
        const int k = s * 16 + aq * 4;
        pa0[r] = (k < F_) ? *(const float4*)&x[(size_t)(m0 + ar0) * F_ + k]
                          : make_float4(0.f, 0.f, 0.f, 0.f);
        pa1[r] = (k < F_) ? *(const float4*)&x[(size_t)(m0 + ar1) * F_ + k]
                          : make_float4(0.f, 0.f, 0.f, 0.f);
        pbv[r] = *(const uint4*)&g_wbf[((size_t)s * 256 + n0 + brow) * 8 +
                                       bhalf * 4];
    };
    auto sts = [&](int buf, int r) {
        As[buf][ar0 * ASTR + aq * 2]     = pack_bf16(pa0[r].x, pa0[r].y);
        As[buf][ar0 * ASTR + aq * 2 + 1] = pack_bf16(pa0[r].z, pa0[r].w);
        As[buf][ar1 * ASTR + aq * 2]     = pack_bf16(pa1[r].x, pa1[r].y);
        As[buf][ar1 * ASTR + aq * 2 + 1] = pack_bf16(pa1[r].z, pa1[r].w);
        *(uint4*)&Bs[buf][brow * ASTR + bhalf * 4] = pbv[r];
    };

    // ldmatrix per-lane byte offsets (constant across steps; parity = buffer)
    const unsigned asu[2] = { smem_u32(&As[0][0]), smem_u32(&As[1][0]) };
    const unsigned bsu[2] = { smem_u32(&Bs[0][0]), smem_u32(&Bs[1][0]) };
    unsigned aOff[4], bOff[2];
    #pragma unroll
    for (int mi = 0; mi < 4; mi++)
        aOff[mi] = (unsigned)((wm * 64 + mi * 16 + (lane & 15)) * (ASTR * 4) +
                              ((lane & 16) ? 16 : 0));
    #pragma unroll
    for (int nj = 0; nj < 2; nj++)
        bOff[nj] = (unsigned)((wn * 32 + nj * 16 + ((lane >> 4) & 1) * 8 +
                               (lane & 7)) * (ASTR * 4) +
                              ((lane & 8) ? 16 : 0));

    float c[4][4][4];
    #pragma unroll
    for (int i = 0; i < 4; i++)
        #pragma unroll
        for (int j = 0; j < 4; j++)
            #pragma unroll
            for (int r = 0; r < 4; r++) c[i][j][r] = 0.f;

    // preamble: step0 -> buf0; step1 -> regs[0]
    ldg(0, 0);
    sts(0, 0);
    ldg(1, 0);
    __syncthreads();

    int p = 0;
    for (int s = 0; s < 9; ++s) {
        if (s < 7) ldg(s + 2, (s + 1) & 1);   // 2 steps ahead

        unsigned a[4][4], bf[4][2];
        #pragma unroll
        for (int mi = 0; mi < 4; mi++)
            LDSM_X4(a[mi][0], a[mi][1], a[mi][2], a[mi][3], asu[p] + aOff[mi]);
        #pragma unroll
        for (int nj = 0; nj < 2; nj++)
            LDSM_X4(bf[2 * nj][0], bf[2 * nj][1], bf[2 * nj + 1][0],
                    bf[2 * nj + 1][1], bsu[p] + bOff[nj]);

        #pragma unroll
        for (int mi = 0; mi < 4; mi++)
            #pragma unroll
            for (int ni = 0; ni < 4; ni++) {
                asm volatile(
                    "mma.sync.aligned.m16n8k16.row.col.f32.bf16.bf16.f32 "
                    "{%0,%1,%2,%3}, {%4,%5,%6,%7}, {%8,%9}, {%0,%1,%2,%3};\n"
                    : "+f"(c[mi][ni][0]), "+f"(c[mi][ni][1]),
                      "+f"(c[mi][ni][2]), "+f"(c[mi][ni][3])
                    : "r"(a[mi][0]), "r"(a[mi][1]), "r"(a[mi][2]), "r"(a[mi][3]),
                      "r"(bf[ni][0]), "r"(bf[ni][1]));
            }

        if (s < 8) sts(1 - p, s & 1);         // stash step s+1
        __syncthreads();
        p ^= 1;
    }

    // epilogue: pack bf16 pairs, store as u32
    unsigned* yw = reinterpret_cast<unsigned*>(g_ybf);
    #pragma unroll
    for (int mi = 0; mi < 4; mi++) {
        int r0 = m0 + wm * 64 + mi * 16 + g;
        #pragma unroll
        for (int ni = 0; ni < 4; ni++) {
            int col = n0 + wn * 32 + ni * 8 + 2 * tig;
            yw[((size_t)r0 * D_ + col) >> 1] =
                pack_bf16(c[mi][ni][0], c[mi][ni][1]);
            yw[((size_t)(r0 + 8) * D_ + col) >> 1] =
                pack_bf16(c[mi][ni][2], c[mi][ni][3]);
        }
    }
}

// ---------------------------------------------------------------------------
// fused LIF kernel: grid (B, NCH) x 256 threads
// ---------------------------------------------------------------------------
template <bool GUARD>
__device__ __forceinline__ void lif1_main(const __nv_bfloat16* __restrict__ yp,
                                          const float* ac, float base,
                                          float& v, float& w0, float& w1,
                                          float& w2, float& w3, float& w4,
                                          float& w5, float& w6,
                                          int ts2, int tend, unsigned* smk,
                                          unsigned& locOr, int warp, int lane) {
    for (int t0 = ts2; t0 < tend; t0 += 4) {
        float nf[4];
        #pragma unroll
        for (int j = 0; j < 4; j++) {
            int t = t0 + 4 + j;
            if (GUARD)
                nf[j] = (t < T_) ? __bfloat162float(yp[(size_t)t * D_]) : 0.f;
            else
                nf[j] = __bfloat162float(yp[(size_t)t * D_]);
        }
        #pragma unroll
        for (int j = 0; j < 4; j++) {
            float acc = base;
            acc = fmaf(w0, ac[0], acc); acc = fmaf(w1, ac[1], acc);
            acc = fmaf(w2, ac[2], acc); acc = fmaf(w3, ac[3], acc);
            acc = fmaf(w4, ac[4], acc); acc = fmaf(w5, ac[5], acc);
            acc = fmaf(w6, ac[6], acc);
            v = fmaf(v, 0.5f, acc);
            bool s = (v >= 1.0f);
            unsigned bal = __ballot_sync(0xffffffffu, s);
            if (s) v = 0.f;
            if (lane == 0) { smk[(t0 + j - ts2) * 8 + warp] = bal; locOr |= bal; }
            w0 = w1; w1 = w2; w2 = w3; w3 = w4; w4 = w5; w5 = w6; w6 = nf[j];
        }
    }
}

__global__ __launch_bounds__(256) void k_lif(const float* __restrict__ pw_b,
                                             const float* __restrict__ dw,
                                             const float* __restrict__ g1,
                                             const float* __restrict__ b1,
                                             const float* __restrict__ m1,
                                             const float* __restrict__ v1,
                                             const float* __restrict__ g2,
                                             const float* __restrict__ b2,
                                             const float* __restrict__ m2,
                                             const float* __restrict__ v2p,
                                             float* __restrict__ out) {
    __shared__ unsigned smk[SMT * 8];
    __shared__ unsigned s_any;
    __shared__ unsigned s_hot;

    const int b    = blockIdx.x;
    const int ch   = blockIdx.y;
    const int d    = threadIdx.x;
    const int lane = d & 31;
    const int warp = d >> 5;

    const int tstart = ch * CLEN;
    const int tend   = tstart + CLEN;
    const int ts2    = (ch == 0) ? 0 : tstart - WARM2;
    const int ts1    = (ch == 0) ? 0 : ts2 - WARM1;

    if (d == 0) { s_any = 0u; s_hot = 0u; }

    const float scale2 = g2[d] * rsqrtf(v2p[d] + 1e-5f);
    const float shift2 = b2[d] - m2[d] * scale2;
    {
        unsigned hot = __ballot_sync(0xffffffffu, shift2 >= 1.0f);
        if (lane == 0 && hot) atomicOr(&s_hot, hot);
    }

    // ---- phase 1: depthwise conv + BN1 + LIF1 ----
    {
        const float bias  = pw_b[d];
        const float scale = g1[d] * rsqrtf(v1[d] + 1e-5f);
        const float shift = b1[d] - m1[d] * scale;

        float ac[K_];
        float suma = 0.f;
        #pragma unroll
        for (int k = 0; k < K_; k++) {
            float a = dw[d * K_ + k];
            suma += a;
            ac[k] = 0.5f * scale * a;
        }
        const float base = 0.5f * (scale * bias * suma + shift);

        const __nv_bfloat16* yp = g_ybf + (size_t)b * T_ * D_ + d;

        float w0, w1, w2, w3, w4, w5, w6;
        {
            float wv[7];
            #pragma unroll
            for (int j = 0; j < 7; j++) {
                int t = ts1 - 3 + j;
                wv[j] = (t >= 0) ? __bfloat162float(yp[(size_t)t * D_]) : 0.f;
            }
            w0 = wv[0]; w1 = wv[1]; w2 = wv[2]; w3 = wv[3];
            w4 = wv[4]; w5 = wv[5]; w6 = wv[6];
        }

        float v = 0.f;
        for (int t0 = ts1; t0 < ts2; t0 += 4) {
            float nf[4];
            #pragma unroll
            for (int j = 0; j < 4; j++)
                nf[j] = __bfloat162float(yp[(size_t)(t0 + 4 + j) * D_]);
            #pragma unroll
            for (int j = 0; j < 4; j++) {
                float acc = base;
                acc = fmaf(w0, ac[0], acc); acc = fmaf(w1, ac[1], acc);
                acc = fmaf(w2, ac[2], acc); acc = fmaf(w3, ac[3], acc);
                acc = fmaf(w4, ac[4], acc); acc = fmaf(w5, ac[5], acc);
                acc = fmaf(w6, ac[6], acc);
                v = fmaf(v, 0.5f, acc);
                if (v >= 1.0f) v = 0.f;
                w0 = w1; w1 = w2; w2 = w3; w3 = w4; w4 = w5; w5 = w6; w6 = nf[j];
            }
        }

        unsigned locOr = 0u;
        if (ch == NCH - 1)
            lif1_main<true >(yp, ac, base, v, w0, w1, w2, w3, w4, w5, w6,
                             ts2, tend, smk, locOr, warp, lane);
        else
            lif1_main<false>(yp, ac, base, v, w0, w1, w2, w3, w4, w5, w6,
                             ts2, tend, smk, locOr, warp, lane);

        if (lane == 0 && locOr) atomicOr(&s_any, locOr);
    }
    __syncthreads();

    // ---- phase 2: sparse linear + BN2 + LIF2 + residual ----
    if (s_any == 0u) {
        if (s_hot == 0u) {
            float4* ob = (float4*)(out + (size_t)tstart * (B_ * D_) +
                                   (size_t)b * D_) + (d & 63);
            const int tof = d >> 6;
            const float4 z = make_float4(0.f, 0.f, 0.f, 0.f);
            #pragma unroll
            for (int jj = 0; jj < CLEN / 4; ++jj)
                ob[(size_t)(jj * 4 + tof) * (B_ * D_ / 4)] = z;
        } else {
            float* op = out + (size_t)tstart * (B_ * D_) + (size_t)b * D_ + d;
            if (shift2 < 1.0f) {
                #pragma unroll 10
                for (int j = 0; j < CLEN; ++j)
                    op[(size_t)j * (B_ * D_)] = 0.f;
            } else {
                float v = 0.f;
                const float hs = 0.5f * shift2;
                for (int j = 0; j < tstart - ts2; ++j) {
                    v = fmaf(v, 0.5f, hs);
                    if (v >= 1.0f) v = 0.f;
                }
                #pragma unroll 10
                for (int j = 0; j < CLEN; ++j) {
                    v = fmaf(v, 0.5f, hs);
                    float sp = 0.f;
                    if (v >= 1.0f) { sp = 1.f; v = 0.f; }
                    op[(size_t)j * (B_ * D_)] = sp;
                }
            }
        }
        return;
    }

    // slow path: spikes present in window
    const int e = d;
    const int      myw   = e >> 5;
    const unsigned mybit = 1u << (e & 31);
    float v = 0.f;

    for (int t = ts2; t < tend; ++t) {
        const int o = (t - ts2) * 8;
        uint4 p0 = *(const uint4*)&smk[o];
        uint4 p1 = *(const uint4*)&smk[o + 4];
        unsigned any = p0.x | p0.y | p0.z | p0.w | p1.x | p1.y | p1.z | p1.w;

        float acc = 0.f, res = 0.f;
        if (any) {
            unsigned wds[8] = {p0.x, p0.y, p0.z, p0.w, p1.x, p1.y, p1.z, p1.w};
            #pragma unroll
            for (int i = 0; i < 8; i++) {
                unsigned wd = wds[i];
                if (i == myw && (wd & mybit)) res = 1.f;
                while (wd) {
                    int bit = __ffs(wd) - 1;
                    wd &= wd - 1;
                    acc += g_linT[(size_t)(i * 32 + bit) * D_ + e];
                }
            }
        }

        float u = fmaf(acc, scale2, shift2);
        v = 0.5f * (v + u);
        float sp = 0.f;
        if (v >= 1.0f) { sp = 1.f; v = 0.f; }

        if (t >= tstart)
            out[((size_t)t * B_ + b) * D_ + e] = sp + res;
    }
}

// ---------------------------------------------------------------------------
// inputs: 0:x 1:pw_w 2:pw_b 3:dw_w 4:bn1_g 5:bn1_b 6:bn1_m 7:bn1_v
//         8:lin_w 9:bn2_g 10:bn2_b 11:bn2_m 12:bn2_v
// ---------------------------------------------------------------------------
extern "C" void kernel_launch(void* const* d_in, const int* in_sizes, int n_in,
                              void* d_out, int out_size) {
    const float* x    = (const float*)d_in[0];
    const float* pw_w = (const float*)d_in[1];
    const float* pw_b = (const float*)d_in[2];
    const float* dw_w = (const float*)d_in[3];
    const float* g1   = (const float*)d_in[4];
    const float* b1   = (const float*)d_in[5];
    const float* m1   = (const float*)d_in[6];
    const float* v1   = (const float*)d_in[7];
    const float* linw = (const float*)d_in[8];
    const float* g2   = (const float*)d_in[9];
    const float* b2   = (const float*)d_in[10];
    const float* m2   = (const float*)d_in[11];
    const float* v2   = (const float*)d_in[12];
    float* out = (float*)d_out;

    k_prep<<<256, 160>>>(pw_w);

    dim3 gg((B_ * T_) / 128, D_ / 128);   // (500, 2)
    k_gemm1<<<gg, 256>>>(x, linw);

    dim3 gl(B_, NCH);
    k_lif<<<gl, 256>>>(pw_b, dw_w, g1, b1, m1, v1, g2, b2, m2, v2, out);
}